// round 1
// baseline (speedup 1.0000x reference)
#include <cuda_runtime.h>
#include <math.h>
#include <stdint.h>

#define BB 4
#define NN 25600
#define DD 64
#define RR (3*NN)
#define SPLIT 96
#define KT 32
#define NSWEEP 8

// scratch (static device globals; no runtime allocation)
__device__ float g_P[(size_t)BB*RR*DD];      // LJ rows   [B][N][3][64]
__device__ float g_Z[(size_t)BB*RR*DD];      // Lc^-1 * BTJ rows
__device__ float g_part[(size_t)BB*SPLIT*DD*DD];
__device__ float g_M[BB*DD*DD];
__device__ float g_trace[BB];
__device__ int   g_rowptr[NN+1];

// Build CSR row pointers from the lexicographically sorted e0 array.
__global__ void k_rowptr(const int* __restrict__ e0, int E){
  int i = blockIdx.x*blockDim.x + threadIdx.x;
  if(i >= E) return;
  int cur  = e0[i];
  int prev = (i==0) ? -1 : e0[i-1];
  for(int n = prev+1; n <= cur; n++) g_rowptr[n] = i;
  if(i == E-1){
    for(int n = cur+1; n <= NN; n++) g_rowptr[n] = E;
  }
}

// One warp per (batch, node). Each lane owns 2 adjacent columns (float2).
// Computes P = LJ and Z = Lc^{-1} * BTJ (so Z^T Z = BTJ^T Cinv BTJ).
__global__ void k_phaseA(const float* __restrict__ x, const float* __restrict__ J,
                         const int* __restrict__ e1)
{
  int gw   = (blockIdx.x*blockDim.x + threadIdx.x) >> 5;
  int lane = threadIdx.x & 31;
  if(gw >= BB*NN) return;
  int b = gw / NN;
  int n = gw - b*NN;

  const float* xb = x + (size_t)b*NN*3;
  const float* Jb = J + (size_t)b*RR*DD;
  int rs = g_rowptr[n], re = g_rowptr[n+1];
  float deg = (float)(re - rs);
  float xn0 = xb[3*n], xn1 = xb[3*n+1], xn2 = xb[3*n+2];

  float g10x=0,g10y=0,g11x=0,g11y=0,g12x=0,g12y=0;   // sum_m J3[m]
  float g20x=0,g20y=0,g21x=0,g21y=0,g22x=0,g22y=0;   // sum_m skew(v) J3[m]
  float c00=0,c11=0,c22=0,c01=0,c02=0,c12=0;         // C accumulator
  float vs0=0,vs1=0,vs2=0;                            // sum_m v

  for(int e = rs; e < re; e++){
    int m = e1[e];
    float v0 = xn0 - xb[3*m];
    float v1 = xn1 - xb[3*m+1];
    float v2 = xn2 - xb[3*m+2];
    const float2* Jm = reinterpret_cast<const float2*>(Jb + (size_t)m*192);
    float2 j0 = Jm[lane];
    float2 j1 = Jm[32+lane];
    float2 j2 = Jm[64+lane];
    g10x += j0.x; g10y += j0.y;
    g11x += j1.x; g11y += j1.y;
    g12x += j2.x; g12y += j2.y;
    // skew(v) rows: [0,-v2,v1],[v2,0,-v0],[-v1,v0,0]
    g20x += v1*j2.x - v2*j1.x;  g20y += v1*j2.y - v2*j1.y;
    g21x += v2*j0.x - v0*j2.x;  g21y += v2*j0.y - v0*j2.y;
    g22x += v0*j1.x - v1*j0.x;  g22y += v0*j1.y - v1*j0.y;
    float vv = v0*v0 + v1*v1 + v2*v2;
    c00 += vv - v0*v0;
    c11 += vv - v1*v1;
    c22 += vv - v2*v2;
    c01 -= v0*v1; c02 -= v0*v2; c12 -= v1*v2;
    vs0 += v0; vs1 += v1; vs2 += v2;
  }

  const float2* Jn = reinterpret_cast<const float2*>(Jb + (size_t)n*192);
  float2 a0 = Jn[lane], a1 = Jn[32+lane], a2 = Jn[64+lane];

  // P = 2*(deg*J3n - sum_m J3[m])
  float2* Pp = reinterpret_cast<float2*>(g_P + ((size_t)b*NN + n)*192);
  float2 p0, p1, p2;
  p0.x = 2.f*(deg*a0.x - g10x); p0.y = 2.f*(deg*a0.y - g10y);
  p1.x = 2.f*(deg*a1.x - g11x); p1.y = 2.f*(deg*a1.y - g11y);
  p2.x = 2.f*(deg*a2.x - g12x); p2.y = 2.f*(deg*a2.y - g12y);
  Pp[lane] = p0; Pp[32+lane] = p1; Pp[64+lane] = p2;

  // Q = g2 - skew(vsum) * J3n
  float q0x = g20x - (vs1*a2.x - vs2*a1.x);
  float q0y = g20y - (vs1*a2.y - vs2*a1.y);
  float q1x = g21x - (vs2*a0.x - vs0*a2.x);
  float q1y = g21y - (vs2*a0.y - vs0*a2.y);
  float q2x = g22x - (vs0*a1.x - vs1*a0.x);
  float q2y = g22y - (vs0*a1.y - vs1*a0.y);

  // Cholesky C = L L^T  (C SPD for generic positions)
  float l00 = sqrtf(fmaxf(c00, 1e-30f));
  float i00 = 1.f/l00;
  float l10 = c01*i00, l20 = c02*i00;
  float l11 = sqrtf(fmaxf(c11 - l10*l10, 1e-30f));
  float i11 = 1.f/l11;
  float l21 = (c12 - l20*l10)*i11;
  float l22 = sqrtf(fmaxf(c22 - l20*l20 - l21*l21, 1e-30f));
  float i22 = 1.f/l22;

  // Z = L^{-1} Q (forward substitution per column)
  float2 z0, z1, z2;
  z0.x = q0x*i00;                             z0.y = q0y*i00;
  z1.x = (q1x - l10*z0.x)*i11;                z1.y = (q1y - l10*z0.y)*i11;
  z2.x = (q2x - l20*z0.x - l21*z1.x)*i22;     z2.y = (q2y - l20*z0.y - l21*z1.y)*i22;

  float2* Zp = reinterpret_cast<float2*>(g_Z + ((size_t)b*NN + n)*192);
  Zp[lane] = z0; Zp[32+lane] = z1; Zp[64+lane] = z2;
}

// M_partial = sum_rows (J_row (x) P_row - Z_row (x) Z_row), split-K over row tiles.
__global__ void k_gram(const float* __restrict__ J){
  __shared__ float sJ[KT*64], sP[KT*64], sZ[KT*64];
  int b   = blockIdx.y;
  int tid = threadIdx.x;
  int tx  = tid & 15, ty = tid >> 4;

  const float4* gJ = reinterpret_cast<const float4*>(J   + (size_t)b*RR*DD);
  const float4* gP = reinterpret_cast<const float4*>(g_P + (size_t)b*RR*DD);
  const float4* gZ = reinterpret_cast<const float4*>(g_Z + (size_t)b*RR*DD);
  float4* s4J = reinterpret_cast<float4*>(sJ);
  float4* s4P = reinterpret_cast<float4*>(sP);
  float4* s4Z = reinterpret_cast<float4*>(sZ);

  float acc[4][4];
  #pragma unroll
  for(int i=0;i<4;i++)
    #pragma unroll
    for(int j=0;j<4;j++) acc[i][j] = 0.f;

  const int ntiles = RR/KT;   // 2400, exact
  for(int t = blockIdx.x; t < ntiles; t += SPLIT){
    size_t base4 = (size_t)t*KT*16;
    __syncthreads();
    #pragma unroll
    for(int i=0;i<2;i++){
      int idx = tid + i*256;
      s4J[idx] = gJ[base4+idx];
      s4P[idx] = gP[base4+idx];
      s4Z[idx] = gZ[base4+idx];
    }
    __syncthreads();
    #pragma unroll 4
    for(int k=0;k<KT;k++){
      float4 av = s4J[k*16+ty];
      float4 zr = s4Z[k*16+ty];
      float4 bv = s4P[k*16+tx];
      float4 zc = s4Z[k*16+tx];
      float a [4] = {av.x, av.y, av.z, av.w};
      float nz[4] = {-zr.x, -zr.y, -zr.z, -zr.w};
      float bbv[4] = {bv.x, bv.y, bv.z, bv.w};
      float zzv[4] = {zc.x, zc.y, zc.z, zc.w};
      #pragma unroll
      for(int i=0;i<4;i++)
        #pragma unroll
        for(int j=0;j<4;j++){
          acc[i][j] = fmaf(a[i],  bbv[j], acc[i][j]);
          acc[i][j] = fmaf(nz[i], zzv[j], acc[i][j]);
        }
    }
  }
  float* outp = g_part + ((size_t)(b*SPLIT + blockIdx.x))*DD*DD;
  #pragma unroll
  for(int i=0;i<4;i++)
    #pragma unroll
    for(int j=0;j<4;j++)
      outp[(ty*4+i)*64 + (tx*4+j)] = acc[i][j];
}

// Deterministic reduction of split-K partials.
__global__ void k_reduce(){
  int idx = blockIdx.x*blockDim.x + threadIdx.x;
  if(idx >= BB*DD*DD) return;
  int b = idx >> 12;
  int e = idx & 4095;
  float s = 0.f;
  for(int sp = 0; sp < SPLIT; sp++)
    s += g_part[((size_t)(b*SPLIT + sp))*4096 + e];
  g_M[idx] = s;
}

// Parallel cyclic Jacobi eigensolver, one block per batch matrix (64x64).
__global__ void k_eig(){
  __shared__ float s[64][65];
  __shared__ float rc[32], rsn[32];
  __shared__ int   rp[32], rq[32];
  __shared__ float red[2];
  int b = blockIdx.x;
  int tid = threadIdx.x;
  const float* Mb = g_M + b*4096;
  for(int i = tid; i < 4096; i += 256){
    int r = i >> 6, c = i & 63;
    s[r][c] = 0.5f*(Mb[r*64+c] + Mb[c*64+r]);   // symmetrize
  }
  __syncthreads();

  for(int sweep = 0; sweep < NSWEEP; sweep++){
    for(int r = 0; r < 63; r++){
      if(tid < 32){
        int t = tid;
        int p = (t==0) ? 0 : 1 + ((t-1+r) % 63);
        int q = 1 + ((62 - t + r) % 63);
        if(p > q){ int tmp = p; p = q; q = tmp; }
        float app = s[p][p], aqq = s[q][q], apq = s[p][q];
        float c = 1.f, sn = 0.f;
        if(fabsf(apq) > 0.f){
          float tau = (aqq - app)/(2.f*apq);
          float tt  = ((tau >= 0.f) ? 1.f : -1.f)/(fabsf(tau) + sqrtf(1.f + tau*tau));
          c  = rsqrtf(1.f + tt*tt);
          sn = tt*c;
        }
        rc[t] = c; rsn[t] = sn; rp[t] = p; rq[t] = q;
      }
      __syncthreads();
      // row phase: A <- J^T A
      #pragma unroll
      for(int w = 0; w < 8; w++){
        int job = tid + w*256;
        int t = job >> 6, j = job & 63;
        float c = rc[t], sn = rsn[t];
        int p = rp[t], q = rq[t];
        float a = s[p][j], bb = s[q][j];
        s[p][j] = c*a - sn*bb;
        s[q][j] = sn*a + c*bb;
      }
      __syncthreads();
      // col phase: A <- A J
      #pragma unroll
      for(int w = 0; w < 8; w++){
        int job = tid + w*256;
        int t = job >> 6, i = job & 63;
        float c = rc[t], sn = rsn[t];
        int p = rp[t], q = rq[t];
        float a = s[i][p], bb = s[i][q];
        s[i][p] = c*a - sn*bb;
        s[i][q] = sn*a + c*bb;
      }
      __syncthreads();
    }
  }

  float val = 0.f;
  if(tid < 64){
    float d = s[tid][tid];
    val = (d > 0.f) ? sqrtf(d) : 0.f;
  }
  #pragma unroll
  for(int o = 16; o > 0; o >>= 1) val += __shfl_down_sync(0xffffffff, val, o);
  if(tid == 0)  red[0] = val;
  if(tid == 32) red[1] = val;
  __syncthreads();
  if(tid == 0) g_trace[b] = red[0] + red[1];
}

__global__ void k_final(float* out){
  if(threadIdx.x == 0)
    out[0] = 0.25f*(g_trace[0] + g_trace[1] + g_trace[2] + g_trace[3]);
}

extern "C" void kernel_launch(void* const* d_in, const int* in_sizes, int n_in,
                              void* d_out, int out_size){
  const float* x  = (const float*)d_in[0];
  const float* J  = (const float*)d_in[1];
  const int*   e0 = (const int*)d_in[2];
  const int*   e1 = (const int*)d_in[3];
  int E = in_sizes[2];
  float* out = (float*)d_out;

  k_rowptr<<<(E + 255)/256, 256>>>(e0, E);
  k_phaseA<<<(BB*NN)/8, 256>>>(x, J, e1);
  k_gram<<<dim3(SPLIT, BB), 256>>>(J);
  k_reduce<<<(BB*DD*DD + 255)/256, 256>>>();
  k_eig<<<BB, 256>>>();
  k_final<<<1, 32>>>(out);
}

// round 2
// speedup vs baseline: 1.7864x; 1.7864x over previous
#include <cuda_runtime.h>
#include <math.h>
#include <stdint.h>

#define BB 4
#define NN 25600
#define DD 64
#define RR (3*NN)
#define SPLIT 148
#define NPART (SPLIT*4)
#define KT 32

// scratch (static device globals; no runtime allocation)
__device__ float g_P[(size_t)BB*RR*DD];      // LJ rows   [B][N][3][64]
__device__ float g_Z[(size_t)BB*RR*DD];      // Lc^-1 * BTJ rows
__device__ float g_part[(size_t)BB*NPART*DD*DD];
__device__ float g_M[BB*DD*DD];
__device__ float g_trace[BB];
__device__ int   g_rowptr[NN+1];

#define PK2(dst, lo, hi) asm("mov.b64 %0, {%1,%2};" : "=l"(dst) : "f"(lo), "f"(hi))
#define UPK2(lo, hi, src) asm("mov.b64 {%0,%1}, %2;" : "=f"(lo), "=f"(hi) : "l"(src))
#define FMA2(acc, a, b) asm("fma.rn.f32x2 %0, %1, %2, %0;" : "+l"(acc) : "l"(a), "l"(b))

// Build CSR row pointers from the lexicographically sorted e0 array.
__global__ void k_rowptr(const int* __restrict__ e0, int E){
  int i = blockIdx.x*blockDim.x + threadIdx.x;
  if(i >= E) return;
  int cur  = e0[i];
  int prev = (i==0) ? -1 : e0[i-1];
  for(int n = prev+1; n <= cur; n++) g_rowptr[n] = i;
  if(i == E-1){
    for(int n = cur+1; n <= NN; n++) g_rowptr[n] = E;
  }
}

// One warp per (batch, node). Each lane owns 2 adjacent columns (float2).
// Computes P = LJ and Z = Lc^{-1} * BTJ (so Z^T Z = BTJ^T Cinv BTJ).
__global__ void k_phaseA(const float* __restrict__ x, const float* __restrict__ J,
                         const int* __restrict__ e1)
{
  int gw   = (blockIdx.x*blockDim.x + threadIdx.x) >> 5;
  int lane = threadIdx.x & 31;
  if(gw >= BB*NN) return;
  int b = gw / NN;
  int n = gw - b*NN;

  const float* xb = x + (size_t)b*NN*3;
  const float* Jb = J + (size_t)b*RR*DD;
  int rs = g_rowptr[n], re = g_rowptr[n+1];
  float deg = (float)(re - rs);
  float xn0 = xb[3*n], xn1 = xb[3*n+1], xn2 = xb[3*n+2];

  float g10x=0,g10y=0,g11x=0,g11y=0,g12x=0,g12y=0;   // sum_m J3[m]
  float g20x=0,g20y=0,g21x=0,g21y=0,g22x=0,g22y=0;   // sum_m skew(v) J3[m]
  float c00=0,c11=0,c22=0,c01=0,c02=0,c12=0;         // C accumulator
  float vs0=0,vs1=0,vs2=0;                            // sum_m v

  for(int e = rs; e < re; e++){
    int m = e1[e];
    float v0 = xn0 - xb[3*m];
    float v1 = xn1 - xb[3*m+1];
    float v2 = xn2 - xb[3*m+2];
    const float2* Jm = reinterpret_cast<const float2*>(Jb + (size_t)m*192);
    float2 j0 = Jm[lane];
    float2 j1 = Jm[32+lane];
    float2 j2 = Jm[64+lane];
    g10x += j0.x; g10y += j0.y;
    g11x += j1.x; g11y += j1.y;
    g12x += j2.x; g12y += j2.y;
    // skew(v) rows: [0,-v2,v1],[v2,0,-v0],[-v1,v0,0]
    g20x += v1*j2.x - v2*j1.x;  g20y += v1*j2.y - v2*j1.y;
    g21x += v2*j0.x - v0*j2.x;  g21y += v2*j0.y - v0*j2.y;
    g22x += v0*j1.x - v1*j0.x;  g22y += v0*j1.y - v1*j0.y;
    float vv = v0*v0 + v1*v1 + v2*v2;
    c00 += vv - v0*v0;
    c11 += vv - v1*v1;
    c22 += vv - v2*v2;
    c01 -= v0*v1; c02 -= v0*v2; c12 -= v1*v2;
    vs0 += v0; vs1 += v1; vs2 += v2;
  }

  const float2* Jn = reinterpret_cast<const float2*>(Jb + (size_t)n*192);
  float2 a0 = Jn[lane], a1 = Jn[32+lane], a2 = Jn[64+lane];

  // P = 2*(deg*J3n - sum_m J3[m])
  float2* Pp = reinterpret_cast<float2*>(g_P + ((size_t)b*NN + n)*192);
  float2 p0, p1, p2;
  p0.x = 2.f*(deg*a0.x - g10x); p0.y = 2.f*(deg*a0.y - g10y);
  p1.x = 2.f*(deg*a1.x - g11x); p1.y = 2.f*(deg*a1.y - g11y);
  p2.x = 2.f*(deg*a2.x - g12x); p2.y = 2.f*(deg*a2.y - g12y);
  Pp[lane] = p0; Pp[32+lane] = p1; Pp[64+lane] = p2;

  // Q = g2 - skew(vsum) * J3n
  float q0x = g20x - (vs1*a2.x - vs2*a1.x);
  float q0y = g20y - (vs1*a2.y - vs2*a1.y);
  float q1x = g21x - (vs2*a0.x - vs0*a2.x);
  float q1y = g21y - (vs2*a0.y - vs0*a2.y);
  float q2x = g22x - (vs0*a1.x - vs1*a0.x);
  float q2y = g22y - (vs0*a1.y - vs1*a0.y);

  // Cholesky C = L L^T  (C SPD for generic positions)
  float l00 = sqrtf(fmaxf(c00, 1e-30f));
  float i00 = 1.f/l00;
  float l10 = c01*i00, l20 = c02*i00;
  float l11 = sqrtf(fmaxf(c11 - l10*l10, 1e-30f));
  float i11 = 1.f/l11;
  float l21 = (c12 - l20*l10)*i11;
  float l22 = sqrtf(fmaxf(c22 - l20*l20 - l21*l21, 1e-30f));
  float i22 = 1.f/l22;

  // Z = L^{-1} Q (forward substitution per column)
  float2 z0, z1, z2;
  z0.x = q0x*i00;                             z0.y = q0y*i00;
  z1.x = (q1x - l10*z0.x)*i11;                z1.y = (q1y - l10*z0.y)*i11;
  z2.x = (q2x - l20*z0.x - l21*z1.x)*i22;     z2.y = (q2y - l20*z0.y - l21*z1.y)*i22;

  float2* Zp = reinterpret_cast<float2*>(g_Z + ((size_t)b*NN + n)*192);
  Zp[lane] = z0; Zp[32+lane] = z1; Zp[64+lane] = z2;
}

// M_partial = sum_rows (J_row (x) P_row - Z_row (x) Z_row).
// 256 threads = 4 k-groups of 64; each thread computes an 8x8 output tile
// via packed fma.rn.f32x2 (dual fp32 FMA).
__global__ void __launch_bounds__(256, 1) k_gram(const float* __restrict__ J){
  __shared__ float sJ[KT*64], sP[KT*64], sZ[KT*64];
  int b   = blockIdx.y;
  int tid = threadIdx.x;
  int g   = tid >> 6;          // k-group 0..3
  int t   = tid & 63;
  int ty  = t >> 3;            // row octet 0..7
  int tx  = t & 7;             // col octet 0..7

  const float4* gJ = reinterpret_cast<const float4*>(J   + (size_t)b*RR*DD);
  const float4* gP = reinterpret_cast<const float4*>(g_P + (size_t)b*RR*DD);
  const float4* gZ = reinterpret_cast<const float4*>(g_Z + (size_t)b*RR*DD);
  float4* s4J = reinterpret_cast<float4*>(sJ);
  float4* s4P = reinterpret_cast<float4*>(sP);
  float4* s4Z = reinterpret_cast<float4*>(sZ);

  unsigned long long acc[8][4];
  #pragma unroll
  for(int i=0;i<8;i++)
    #pragma unroll
    for(int j=0;j<4;j++) acc[i][j] = 0ull;

  const int ntiles = RR/KT;   // 2400
  for(int tt = blockIdx.x; tt < ntiles; tt += SPLIT){
    size_t base4 = (size_t)tt*KT*16;
    __syncthreads();
    #pragma unroll
    for(int i=0;i<2;i++){
      int idx = tid + i*256;
      s4J[idx] = gJ[base4+idx];
      s4P[idx] = gP[base4+idx];
      s4Z[idx] = gZ[base4+idx];
    }
    __syncthreads();
    #pragma unroll
    for(int kk=0;kk<8;kk++){
      int k = g*8 + kk;
      float4 ja = s4J[k*16+ty*2], jb = s4J[k*16+ty*2+1];
      float4 za = s4Z[k*16+ty*2], zb = s4Z[k*16+ty*2+1];
      float4 pa = s4P[k*16+tx*2], pb = s4P[k*16+tx*2+1];
      float4 ca = s4Z[k*16+tx*2], cb = s4Z[k*16+tx*2+1];

      unsigned long long ad[8], zd[8], bp[4], zp[4];
      PK2(ad[0], ja.x, ja.x); PK2(ad[1], ja.y, ja.y);
      PK2(ad[2], ja.z, ja.z); PK2(ad[3], ja.w, ja.w);
      PK2(ad[4], jb.x, jb.x); PK2(ad[5], jb.y, jb.y);
      PK2(ad[6], jb.z, jb.z); PK2(ad[7], jb.w, jb.w);
      PK2(zd[0], za.x, za.x); PK2(zd[1], za.y, za.y);
      PK2(zd[2], za.z, za.z); PK2(zd[3], za.w, za.w);
      PK2(zd[4], zb.x, zb.x); PK2(zd[5], zb.y, zb.y);
      PK2(zd[6], zb.z, zb.z); PK2(zd[7], zb.w, zb.w);
      PK2(bp[0], pa.x, pa.y); PK2(bp[1], pa.z, pa.w);
      PK2(bp[2], pb.x, pb.y); PK2(bp[3], pb.z, pb.w);
      float n0 = -ca.x, n1 = -ca.y, n2 = -ca.z, n3 = -ca.w;
      float n4 = -cb.x, n5 = -cb.y, n6 = -cb.z, n7 = -cb.w;
      PK2(zp[0], n0, n1); PK2(zp[1], n2, n3);
      PK2(zp[2], n4, n5); PK2(zp[3], n6, n7);

      #pragma unroll
      for(int ii=0;ii<8;ii++)
        #pragma unroll
        for(int jj=0;jj<4;jj++){
          FMA2(acc[ii][jj], ad[ii], bp[jj]);
          FMA2(acc[ii][jj], zd[ii], zp[jj]);
        }
    }
  }

  float* outp = g_part + ((size_t)b*NPART + (size_t)blockIdx.x*4 + g)*DD*DD;
  #pragma unroll
  for(int ii=0;ii<8;ii++){
    int row = ty*8 + ii;
    #pragma unroll
    for(int jj=0;jj<4;jj++){
      float lo, hi;
      UPK2(lo, hi, acc[ii][jj]);
      outp[row*64 + tx*8 + jj*2]     = lo;
      outp[row*64 + tx*8 + jj*2 + 1] = hi;
    }
  }
}

// Deterministic reduction of split-K partials.
__global__ void k_reduce(){
  int idx = blockIdx.x*blockDim.x + threadIdx.x;
  if(idx >= BB*DD*DD) return;
  int b = idx >> 12;
  int e = idx & 4095;
  float s = 0.f;
  for(int sp = 0; sp < NPART; sp++)
    s += g_part[((size_t)b*NPART + sp)*4096 + e];
  g_M[idx] = s;
}

// Eigenvalues via Householder tridiagonalization + Sturm bisection.
// One block per batch matrix (64x64), 256 threads.
__global__ void k_eig(){
  __shared__ float s[64][65];
  __shared__ float v[64], w[64], dd[64], ee[64], e2[64];
  __shared__ float red[64];
  __shared__ float sc[4];
  __shared__ float bnd[2];
  int b = blockIdx.x;
  int tid = threadIdx.x;
  const float* Mb = g_M + b*4096;
  for(int i = tid; i < 4096; i += 256){
    int r = i >> 6, c = i & 63;
    s[r][c] = 0.5f*(Mb[r*64+c] + Mb[c*64+r]);   // symmetrize
  }
  __syncthreads();

  // Householder tridiagonalization
  for(int k = 0; k < 62; k++){
    int m = 63 - k;
    if(tid < 64){
      float xi = (tid < m) ? s[k+1+tid][k] : 0.f;
      red[tid] = xi*xi;
    }
    __syncthreads();
    if(tid < 32){
      float val = red[tid] + red[tid+32];
      #pragma unroll
      for(int o = 16; o > 0; o >>= 1) val += __shfl_down_sync(0xffffffffu, val, o);
      if(tid == 0){
        float norm2 = val;
        float x0 = s[k+1][k];
        if(norm2 < 1e-28f){
          sc[0] = x0; sc[1] = 0.f; sc[2] = 0.f;
        } else {
          float alpha = (x0 >= 0.f) ? -sqrtf(norm2) : sqrtf(norm2);
          float v0 = x0 - alpha;
          float vtv = 2.f*(norm2 - alpha*x0);
          sc[0] = alpha; sc[1] = 2.f/vtv; sc[2] = v0;
        }
      }
    }
    __syncthreads();
    float beta = sc[1];
    if(tid == 0) ee[k] = sc[0];
    if(beta != 0.f){
      if(tid < 64){
        v[tid] = (tid < m) ? ((tid == 0) ? sc[2] : s[k+1+tid][k]) : 0.f;
      }
      __syncthreads();
      // p = beta * A' v
      if(tid < m){
        int i = k+1+tid;
        float acc0 = 0.f, acc1 = 0.f;
        int j = 0;
        for(; j+1 < m; j += 2){
          acc0 = fmaf(s[i][k+1+j], v[j],   acc0);
          acc1 = fmaf(s[i][k+2+j], v[j+1], acc1);
        }
        if(j < m) acc0 = fmaf(s[i][k+1+j], v[j], acc0);
        float p = beta*(acc0 + acc1);
        w[tid] = p;
        red[tid] = p*v[tid];
      } else if(tid < 64){
        red[tid] = 0.f;
      }
      __syncthreads();
      if(tid < 32){
        float val = red[tid] + red[tid+32];
        #pragma unroll
        for(int o = 16; o > 0; o >>= 1) val += __shfl_down_sync(0xffffffffu, val, o);
        if(tid == 0) sc[3] = val;    // p^T v
      }
      __syncthreads();
      if(tid < m){
        float K = 0.5f*beta*sc[3];
        w[tid] = w[tid] - K*v[tid];
      }
      __syncthreads();
      // rank-2 update: A' -= v w^T + w v^T (256 threads: 64 rows x 4 col-strides)
      {
        int r = tid & 63, q = tid >> 6;
        if(r < m){
          float vr = v[r], wr = w[r];
          for(int j = q; j < m; j += 4){
            s[k+1+r][k+1+j] -= vr*w[j] + wr*v[j];
          }
        }
      }
      __syncthreads();
    } else {
      __syncthreads();
    }
  }
  if(tid == 0) ee[62] = s[63][62];
  __syncthreads();
  if(tid < 64) dd[tid] = s[tid][tid];
  if(tid < 63) e2[tid] = ee[tid]*ee[tid];
  __syncthreads();

  // Gershgorin bounds
  if(tid < 64){
    float el = (tid > 0)  ? fabsf(ee[tid-1]) : 0.f;
    float er = (tid < 63) ? fabsf(ee[tid])   : 0.f;
    red[tid] = dd[tid] - el - er;
    v[tid]   = dd[tid] + el + er;
  }
  __syncthreads();
  if(tid < 32){
    float lo = fminf(red[tid], red[tid+32]);
    float hi = fmaxf(v[tid],   v[tid+32]);
    #pragma unroll
    for(int o = 16; o > 0; o >>= 1){
      lo = fminf(lo, __shfl_down_sync(0xffffffffu, lo, o));
      hi = fmaxf(hi, __shfl_down_sync(0xffffffffu, hi, o));
    }
    if(tid == 0){ bnd[0] = lo; bnd[1] = hi; }
  }
  __syncthreads();

  // Bisection: thread j isolates eigenvalue j
  float val = 0.f;
  if(tid < 64){
    float lo = bnd[0], hi = bnd[1];
    #pragma unroll 1
    for(int it = 0; it < 34; it++){
      float mid = 0.5f*(lo + hi);
      int cnt = 0;
      float q = dd[0] - mid;
      cnt += (q < 0.f);
      #pragma unroll 1
      for(int i = 1; i < 64; i++){
        float aq = fabsf(q);
        float denom = (aq < 1e-25f) ? ((q < 0.f) ? -1e-25f : 1e-25f) : q;
        q = (dd[i] - mid) - __fdividef(e2[i-1], denom);
        cnt += (q < 0.f);
      }
      if(cnt > tid) hi = mid; else lo = mid;
    }
    float lam = 0.5f*(lo + hi);
    val = (lam > 0.f) ? sqrtf(lam) : 0.f;
  }
  if(tid < 64) red[tid] = val;
  __syncthreads();
  if(tid < 32){
    float sum = red[tid] + red[tid+32];
    #pragma unroll
    for(int o = 16; o > 0; o >>= 1) sum += __shfl_down_sync(0xffffffffu, sum, o);
    if(tid == 0) g_trace[b] = sum;
  }
}

__global__ void k_final(float* out){
  if(threadIdx.x == 0)
    out[0] = 0.25f*(g_trace[0] + g_trace[1] + g_trace[2] + g_trace[3]);
}

extern "C" void kernel_launch(void* const* d_in, const int* in_sizes, int n_in,
                              void* d_out, int out_size){
  const float* x  = (const float*)d_in[0];
  const float* J  = (const float*)d_in[1];
  const int*   e0 = (const int*)d_in[2];
  const int*   e1 = (const int*)d_in[3];
  int E = in_sizes[2];
  float* out = (float*)d_out;

  k_rowptr<<<(E + 255)/256, 256>>>(e0, E);
  k_phaseA<<<(BB*NN)/8, 256>>>(x, J, e1);
  k_gram<<<dim3(SPLIT, BB), 256>>>(J);
  k_reduce<<<(BB*DD*DD + 255)/256, 256>>>();
  k_eig<<<BB, 256>>>();
  k_final<<<1, 32>>>(out);
}